// round 13
// baseline (speedup 1.0000x reference)
#include <cuda_runtime.h>
#include <math.h>
#include <stdint.h>

// Problem constants
#define NB 2
#define SSEQ 4096
#define NV 50257
#define NH 1024
#define MASKID 50256
#define TPB 512
#define WPB 16                    // warps per block
#define NROWS (NB * SSEQ)         // 8192
#define NBLK (NROWS / WPB)        // 512
#define CPL 8                     // float4 chunks per lane (1024/4/32)

__device__ __forceinline__ void ins3(float v, int i,
                                     float& v0, int& i0,
                                     float& v1, int& i1,
                                     float& v2, int& i2)
{
    if (v > v0 || (v == v0 && i < i0)) {
        v2 = v1; i2 = i1; v1 = v0; i1 = i0; v0 = v; i0 = i;
    } else if (v > v1 || (v == v1 && i < i1)) {
        v2 = v1; i2 = i1; v1 = v; i1 = i;
    } else if (v > v2 || (v == v2 && i < i2)) {
        v2 = v; i2 = i;
    }
}

__global__ __launch_bounds__(TPB)
void softmask_kernel(const void* __restrict__ x_t_raw,
                     const float* __restrict__ probs,
                     const float* __restrict__ embed,
                     const float* __restrict__ p_os,
                     const float* __restrict__ p_oa,
                     const float* __restrict__ p_ob,
                     float* __restrict__ out)
{
    const int warp = threadIdx.x >> 5;
    const int lane = threadIdx.x & 31;
    const int row  = blockIdx.x * WPB + warp;

    // ---- dtype-width detection + token fetch: lane 0 only, then broadcast ----
    int tok;
    if (lane == 0) {
        const int* xi = (const int*)x_t_raw;
        const bool is64 = (__ldg(&xi[1]) == 0) & (__ldg(&xi[3]) == 0) &
                          (__ldg(&xi[5]) == 0) & (__ldg(&xi[7]) == 0);
        tok = is64 ? (int)__ldg(&((const long long*)x_t_raw)[row])
                   : __ldg(&xi[row]);
    }
    tok = __shfl_sync(0xffffffffu, tok, 0);

    float4* orow = (float4*)(out + (size_t)row * NH);

    if (tok != MASKID) {
        // ---- fast path: 8 front-batched RO-path LDG.128 -> 8 streaming STG.128 ----
        const float4* erow = (const float4*)(embed + (size_t)tok * NH);
        float4 v[CPL];
#pragma unroll
        for (int j = 0; j < CPL; ++j) v[j] = __ldg(&erow[lane + 32 * j]);
#pragma unroll
        for (int j = 0; j < CPL; ++j) __stcs(&orow[lane + 32 * j], v[j]);
        return;
    }

    // ---- rare heavy path: warp-local top-3 + entropy over the vocab row ----
    const float* p = probs + (size_t)row * NV;

    float v0 = -1e30f, v1 = -1e30f, v2 = -1e30f;
    int   i0 = 0x7fffffff, i1 = 0x7fffffff, i2 = 0x7fffffff;
    float ent = 0.0f;

    for (int i = lane; i < NV; i += 32) {
        float v = __ldcs(&p[i]);
        if (v > 0.0f) ent -= v * __logf(v);
        ins3(v, i, v0, i0, v1, i1, v2, i2);
    }
#pragma unroll
    for (int off = 16; off > 0; off >>= 1) {
        ent += __shfl_xor_sync(0xffffffffu, ent, off);
        float ov0 = __shfl_xor_sync(0xffffffffu, v0, off);
        float ov1 = __shfl_xor_sync(0xffffffffu, v1, off);
        float ov2 = __shfl_xor_sync(0xffffffffu, v2, off);
        int   oi0 = __shfl_xor_sync(0xffffffffu, i0, off);
        int   oi1 = __shfl_xor_sync(0xffffffffu, i1, off);
        int   oi2 = __shfl_xor_sync(0xffffffffu, i2, off);
        ins3(ov0, oi0, v0, i0, v1, i1, v2, i2);
        ins3(ov1, oi1, v0, i0, v1, i1, v2, i2);
        ins3(ov2, oi2, v0, i0, v1, i1, v2, i2);
    }

    float ssum = v0 + v1 + v2 + 1e-10f;
    float w0 = v0 / ssum, w1 = v1 / ssum, w2 = v2 / ssum;

    float os = p_os[0], oa = p_oa[0], ob = p_ob[0];
    float sp_oa = (oa > 20.0f) ? oa : log1pf(expf(oa));
    float sp_ob = (ob > 20.0f) ? ob : log1pf(expf(ob));
    float sig_os = 1.0f / (1.0f + expf(-os));
    float arg = sp_oa * (sp_ob - ent);
    float lam = sig_os * (1.0f / (1.0f + expf(-arg)));

    const float4* e0 = (const float4*)(embed + (size_t)i0 * NH);
    const float4* e1 = (const float4*)(embed + (size_t)i1 * NH);
    const float4* e2 = (const float4*)(embed + (size_t)i2 * NH);
    const float4* er = (const float4*)(embed + (size_t)MASKID * NH);

#pragma unroll
    for (int j = 0; j < CPL; ++j) {
        int c = lane + 32 * j;
        float4 a = __ldg(&e0[c]), b = __ldg(&e1[c]);
        float4 cc = __ldg(&e2[c]), r = __ldg(&er[c]);
        float4 o;
        o.x = (1.0f - lam) * r.x + lam * (w0 * a.x + w1 * b.x + w2 * cc.x);
        o.y = (1.0f - lam) * r.y + lam * (w0 * a.y + w1 * b.y + w2 * cc.y);
        o.z = (1.0f - lam) * r.z + lam * (w0 * a.z + w1 * b.z + w2 * cc.z);
        o.w = (1.0f - lam) * r.w + lam * (w0 * a.w + w1 * b.w + w2 * cc.w);
        __stcs(&orow[c], o);
    }
}

extern "C" void kernel_launch(void* const* d_in, const int* in_sizes, int n_in,
                              void* d_out, int out_size)
{
    (void)in_sizes; (void)n_in; (void)out_size;
    const void*  x_t   = d_in[0];
    const float* probs = (const float*)d_in[1];
    const float* embed = (const float*)d_in[2];
    const float* om_s  = (const float*)d_in[3];
    const float* om_a  = (const float*)d_in[4];
    const float* om_b  = (const float*)d_in[5];
    float* out = (float*)d_out;

    softmask_kernel<<<NBLK, TPB>>>(x_t, probs, embed, om_s, om_a, om_b, out);
}

// round 14
// speedup vs baseline: 1.0479x; 1.0479x over previous
#include <cuda_runtime.h>
#include <math.h>
#include <stdint.h>

// Problem constants
#define NB 2
#define SSEQ 4096
#define NV 50257
#define NH 1024
#define MASKID 50256
#define TPB 256
#define WPB 8                     // warps per block
#define NROWS (NB * SSEQ)         // 8192
#define NBLK (NROWS / WPB)        // 1024
#define CPL 8                     // float4 chunks per lane (heavy path)
#define CPL8 4                    // 32-byte chunks per lane (fast path)

// ---- Blackwell 256-bit global ld/st ----
struct f32x8 { float a0,a1,a2,a3,a4,a5,a6,a7; };

__device__ __forceinline__ f32x8 ldg256(const float* p) {
    f32x8 v;
    asm volatile("ld.global.v8.f32 {%0,%1,%2,%3,%4,%5,%6,%7}, [%8];"
                 : "=f"(v.a0), "=f"(v.a1), "=f"(v.a2), "=f"(v.a3),
                   "=f"(v.a4), "=f"(v.a5), "=f"(v.a6), "=f"(v.a7)
                 : "l"(p));
    return v;
}
__device__ __forceinline__ void stg256_cs(float* p, const f32x8& v) {
    asm volatile("st.global.cs.v8.f32 [%0], {%1,%2,%3,%4,%5,%6,%7,%8};"
                 :: "l"(p),
                    "f"(v.a0), "f"(v.a1), "f"(v.a2), "f"(v.a3),
                    "f"(v.a4), "f"(v.a5), "f"(v.a6), "f"(v.a7)
                 : "memory");
}

__device__ __forceinline__ void ins3(float v, int i,
                                     float& v0, int& i0,
                                     float& v1, int& i1,
                                     float& v2, int& i2)
{
    if (v > v0 || (v == v0 && i < i0)) {
        v2 = v1; i2 = i1; v1 = v0; i1 = i0; v0 = v; i0 = i;
    } else if (v > v1 || (v == v1 && i < i1)) {
        v2 = v1; i2 = i1; v1 = v; i1 = i;
    } else if (v > v2 || (v == v2 && i < i2)) {
        v2 = v; i2 = i;
    }
}

__global__ __launch_bounds__(TPB)
void softmask_kernel(const void* __restrict__ x_t_raw,
                     const float* __restrict__ probs,
                     const float* __restrict__ embed,
                     const float* __restrict__ p_os,
                     const float* __restrict__ p_oa,
                     const float* __restrict__ p_ob,
                     float* __restrict__ out)
{
    const int warp = threadIdx.x >> 5;
    const int lane = threadIdx.x & 31;
    const int row  = blockIdx.x * WPB + warp;

    // ---- dtype-width detection (int64 vs int32), per-thread broadcast loads ----
    const int* xi = (const int*)x_t_raw;
    const bool is64 = (xi[1] == 0) & (xi[3] == 0) & (xi[5] == 0) & (xi[7] == 0);
    const int tok = is64 ? (int)((const long long*)x_t_raw)[row] : xi[row];

    if (tok != MASKID) {
        // ---- fast path: 4 front-batched LDG.256 -> 4 streaming STG.256 ----
        const float* erow = embed + (size_t)tok * NH;
        float*       orow = out   + (size_t)row * NH;
        f32x8 v[CPL8];
#pragma unroll
        for (int j = 0; j < CPL8; ++j) v[j] = ldg256(erow + lane * 8 + 256 * j);
#pragma unroll
        for (int j = 0; j < CPL8; ++j) stg256_cs(orow + lane * 8 + 256 * j, v[j]);
        return;
    }

    // ---- rare heavy path: warp-local top-3 + entropy over the vocab row ----
    const float* p = probs + (size_t)row * NV;

    float v0 = -1e30f, v1 = -1e30f, v2 = -1e30f;
    int   i0 = 0x7fffffff, i1 = 0x7fffffff, i2 = 0x7fffffff;
    float ent = 0.0f;

    for (int i = lane; i < NV; i += 32) {
        float v = __ldcs(&p[i]);
        if (v > 0.0f) ent -= v * __logf(v);
        ins3(v, i, v0, i0, v1, i1, v2, i2);
    }
#pragma unroll
    for (int off = 16; off > 0; off >>= 1) {
        ent += __shfl_xor_sync(0xffffffffu, ent, off);
        float ov0 = __shfl_xor_sync(0xffffffffu, v0, off);
        float ov1 = __shfl_xor_sync(0xffffffffu, v1, off);
        float ov2 = __shfl_xor_sync(0xffffffffu, v2, off);
        int   oi0 = __shfl_xor_sync(0xffffffffu, i0, off);
        int   oi1 = __shfl_xor_sync(0xffffffffu, i1, off);
        int   oi2 = __shfl_xor_sync(0xffffffffu, i2, off);
        ins3(ov0, oi0, v0, i0, v1, i1, v2, i2);
        ins3(ov1, oi1, v0, i0, v1, i1, v2, i2);
        ins3(ov2, oi2, v0, i0, v1, i1, v2, i2);
    }

    float ssum = v0 + v1 + v2 + 1e-10f;
    float w0 = v0 / ssum, w1 = v1 / ssum, w2 = v2 / ssum;

    float os = p_os[0], oa = p_oa[0], ob = p_ob[0];
    float sp_oa = (oa > 20.0f) ? oa : log1pf(expf(oa));
    float sp_ob = (ob > 20.0f) ? ob : log1pf(expf(ob));
    float sig_os = 1.0f / (1.0f + expf(-os));
    float arg = sp_oa * (sp_ob - ent);
    float lam = sig_os * (1.0f / (1.0f + expf(-arg)));

    const float4* e0 = (const float4*)(embed + (size_t)i0 * NH);
    const float4* e1 = (const float4*)(embed + (size_t)i1 * NH);
    const float4* e2 = (const float4*)(embed + (size_t)i2 * NH);
    const float4* er = (const float4*)(embed + (size_t)MASKID * NH);
    float4* orow4 = (float4*)(out + (size_t)row * NH);

#pragma unroll
    for (int j = 0; j < CPL; ++j) {
        int c = lane + 32 * j;
        float4 a = e0[c], b = e1[c], cc = e2[c], r = er[c];
        float4 o;
        o.x = (1.0f - lam) * r.x + lam * (w0 * a.x + w1 * b.x + w2 * cc.x);
        o.y = (1.0f - lam) * r.y + lam * (w0 * a.y + w1 * b.y + w2 * cc.y);
        o.z = (1.0f - lam) * r.z + lam * (w0 * a.z + w1 * b.z + w2 * cc.z);
        o.w = (1.0f - lam) * r.w + lam * (w0 * a.w + w1 * b.w + w2 * cc.w);
        __stcs(&orow4[c], o);
    }
}

extern "C" void kernel_launch(void* const* d_in, const int* in_sizes, int n_in,
                              void* d_out, int out_size)
{
    (void)in_sizes; (void)n_in; (void)out_size;
    const void*  x_t   = d_in[0];
    const float* probs = (const float*)d_in[1];
    const float* embed = (const float*)d_in[2];
    const float* om_s  = (const float*)d_in[3];
    const float* om_a  = (const float*)d_in[4];
    const float* om_b  = (const float*)d_in[5];
    float* out = (float*)d_out;

    softmask_kernel<<<NBLK, TPB>>>(x_t, probs, embed, om_s, om_a, om_b, out);
}